// round 2
// baseline (speedup 1.0000x reference)
#include <cuda_runtime.h>

#define BB 64
#define SS 512
#define HH 1024
#define KK 7
#define NCHUNK 16
#define CHUNK 32

// scratch (allocation-free rule: __device__ globals)
__device__ float g_em[BB * SS * KK];         // emissions
__device__ float g_num[BB];                  // numerator per batch
__device__ float g_M[BB * NCHUNK * KK * KK]; // chunk transfer matrices (log2 domain)

// ---------------------------------------------------------------------------
// dtype-width detection (harness may canonicalize bool/int64 -> int32 etc.)
// mask: all entries are 0/1, little-endian. Detect byte stride 1/4/8.
// gt:   values 0..6. Detect int32 (stride 1 word) vs int64 (stride 2 words).
// ---------------------------------------------------------------------------
__device__ __forceinline__ int detect_mask_w(const unsigned char* m) {
    unsigned int or123 = 0, or4 = 0;
#pragma unroll
    for (int off = 0; off < 64; off++) {
        unsigned char v = m[off];
        if (off & 3) or123 |= v;           // offsets not multiple of 4
        else if ((off & 7) == 4) or4 |= v; // offset 4 mod 8
    }
    if (or123) return 1;
    return or4 ? 4 : 8;
}
__device__ __forceinline__ int detect_gt_w(const void* gt) {
    const int* v = (const int*)gt;
    int orv = 0;
#pragma unroll
    for (int q = 0; q < 64; q++) orv |= v[2 * q + 1];
    return (orv == 0) ? 2 : 1; // stride in 32-bit words
}
__device__ __forceinline__ int gt_read(const void* gt, long idx, int gw) {
    return ((const int*)gt)[idx * gw];
}
__device__ __forceinline__ int mask_read(const unsigned char* m, long idx, int mw) {
    return m[idx * mw];
}

// ---------------------------------------------------------------------------
// K1: emissions[b,s,k] = sum_h x[b,s,h]*W[h,k] + b[k]
// 128 threads/block; thread t owns h = t*4+q + jj*512 (float4 loads),
// W slice (56 floats) in registers. DRAM-bound design.
// ---------------------------------------------------------------------------
__global__ __launch_bounds__(128) void k_emis(const float4* __restrict__ x4,
                                              const float* __restrict__ W,
                                              const float* __restrict__ bias,
                                              int rows_per_block) {
    const int t = threadIdx.x;
    const long row0 = (long)blockIdx.x * rows_per_block;

    float w[2][4][7];
#pragma unroll
    for (int jj = 0; jj < 2; jj++)
#pragma unroll
        for (int q = 0; q < 4; q++)
#pragma unroll
            for (int k = 0; k < 7; k++)
                w[jj][q][k] = W[(t * 4 + q + jj * 512) * 7 + k];

    float bk = (t < 7) ? bias[t] : 0.f;
    __shared__ float wsum[4][8];

    float4 xv[2];
#pragma unroll
    for (int jj = 0; jj < 2; jj++) xv[jj] = x4[row0 * 256 + t + jj * 128];

    for (int r = 0; r < rows_per_block; r++) {
        float4 xn[2];
        if (r + 1 < rows_per_block) {
#pragma unroll
            for (int jj = 0; jj < 2; jj++)
                xn[jj] = x4[(row0 + r + 1) * 256 + t + jj * 128];
        }
        float acc[7];
#pragma unroll
        for (int k = 0; k < 7; k++) acc[k] = 0.f;
#pragma unroll
        for (int jj = 0; jj < 2; jj++) {
            const float xq[4] = {xv[jj].x, xv[jj].y, xv[jj].z, xv[jj].w};
#pragma unroll
            for (int q = 0; q < 4; q++)
#pragma unroll
                for (int k = 0; k < 7; k++)
                    acc[k] = fmaf(xq[q], w[jj][q][k], acc[k]);
        }

        // warp butterfly: every lane ends with full warp sum per k
#pragma unroll
        for (int off = 16; off > 0; off >>= 1)
#pragma unroll
            for (int k = 0; k < 7; k++)
                acc[k] += __shfl_xor_sync(0xffffffffu, acc[k], off);

        const int warp = t >> 5, lane = t & 31;
        if (lane < 7) wsum[warp][lane] = acc[lane];
        __syncthreads();
        if (t < 7) {
            g_em[(row0 + r) * 7 + t] =
                wsum[0][t] + wsum[1][t] + wsum[2][t] + wsum[3][t] + bk;
        }
        __syncthreads();
#pragma unroll
        for (int jj = 0; jj < 2; jj++) xv[jj] = xn[jj];
    }
}

// ---------------------------------------------------------------------------
// K2: numerator per batch
// ---------------------------------------------------------------------------
__global__ __launch_bounds__(256) void k_num(const void* __restrict__ gt,
                                             const unsigned char* __restrict__ mask,
                                             const float* __restrict__ start_t,
                                             const float* __restrict__ end_t,
                                             const float* __restrict__ trans) {
    const int b = blockIdx.x, tid = threadIdx.x;
    __shared__ int s_gw, s_mw;
    if (tid == 0) { s_gw = detect_gt_w(gt); s_mw = detect_mask_w(mask); }
    __syncthreads();
    const int gw = s_gw, mw = s_mw;

    const long gbase = (long)b * SS;
    const float* emb = g_em + gbase * KK;

    float s = 0.f;
    int cnt = 0;
    for (int t = tid; t < SS; t += 256) {
        int gc = gt_read(gt, gbase + t, gw);
        int m = mask_read(mask, gbase + t, mw) ? 1 : 0;
        cnt += m;
        if (t == 0) {
            s += start_t[gc] + emb[gc];
        } else {
            int gp = gt_read(gt, gbase + t - 1, gw);
            s += m ? (trans[gp * 7 + gc] + emb[t * 7 + gc]) : 0.f;
        }
    }
#pragma unroll
    for (int off = 16; off; off >>= 1) {
        s += __shfl_xor_sync(0xffffffffu, s, off);
        cnt += __shfl_xor_sync(0xffffffffu, cnt, off);
    }
    __shared__ float ssh[8];
    __shared__ int csh[8];
    const int warp = tid >> 5, lane = tid & 31;
    if (lane == 0) { ssh[warp] = s; csh[warp] = cnt; }
    __syncthreads();
    if (tid == 0) {
        float st = 0.f;
        int ct = 0;
#pragma unroll
        for (int wdx = 0; wdx < 8; wdx++) { st += ssh[wdx]; ct += csh[wdx]; }
        int last = ct - 1;
        g_num[b] = st + end_t[gt_read(gt, gbase + last, gw)];
    }
}

// ---------------------------------------------------------------------------
// K3: per-chunk 7x7 transfer matrix via SCALED forward (linear domain,
// integer-exponent renorm). Thread (i,j) of 64-thread block holds P[i][j].
// Output in log2 domain: M[i][j] = mexp + log2(P[i][j]).  grid=(NCHUNK,BB)
// ---------------------------------------------------------------------------
__global__ __launch_bounds__(64) void k_chunk(const unsigned char* __restrict__ mask,
                                              const float* __restrict__ trans) {
    const int c = blockIdx.x, b = blockIdx.y;
    const int tid = threadIdx.x;
    const int i = tid >> 3, j = tid & 7;
    const bool act = (i < 7) && (j < 7);
    const float L2E = 1.4426950408889634f;

    __shared__ float Psh[8][8];
    __shared__ int s_mw;
    if (tid == 0) s_mw = detect_mask_w(mask);

    float Tr[7];
#pragma unroll
    for (int k = 0; k < 7; k++)
        Tr[k] = act ? exp2f(trans[k * 7 + j] * L2E) : 0.f;

    float v = (act && i == j) ? 1.f : 0.f;
    int mexp = 0;
    Psh[i][j] = v;
    __syncthreads();
    const int mw = s_mw;

    const int t0 = 1 + c * CHUNK;
    const int t1 = (t0 + CHUNK < SS) ? (t0 + CHUNK) : SS;

    float em_n = act ? g_em[((long)b * SS + t0) * KK + j] : 0.f;
    int mk_n = mask_read(mask, (long)b * SS + t0, mw);

    for (int t = t0; t < t1; t++) {
        const float em_c = em_n;
        const int mk = mk_n;
        if (t + 1 < t1) {
            em_n = act ? g_em[((long)b * SS + t + 1) * KK + j] : 0.f;
            mk_n = mask_read(mask, (long)b * SS + t + 1, mw);
        }
        float row[7];
#pragma unroll
        for (int k = 0; k < 7; k++) row[k] = Psh[i][k];
        __syncthreads();

        if (mk) {  // uniform across block
            float nv = 0.f;
#pragma unroll
            for (int k = 0; k < 7; k++) nv = fmaf(row[k], Tr[k], nv);
            nv *= exp2f(em_c * L2E);
            float rs = nv;
#pragma unroll
            for (int off = 4; off; off >>= 1)
                rs += __shfl_xor_sync(0xffffffffu, rs, off, 8);
            int eb = ((__float_as_int(rs) >> 23) & 255) - 127;
            eb = (rs > 0.f) ? eb : 0;
            float scl = __int_as_float((127 - eb) << 23);  // 2^-eb
            v = nv * scl;
            mexp += eb;
        }
        Psh[i][j] = v;
        __syncthreads();
    }
    if (act)
        g_M[(((long)b * NCHUNK + c) * 7 + i) * 7 + j] = (float)mexp + log2f(v);
}

// ---------------------------------------------------------------------------
// K4: combine chunk matrices (log2 LSE), denominator, llh, mean.
// Single block of 512 threads: b = tid>>3, j = tid&7.
// ---------------------------------------------------------------------------
__global__ __launch_bounds__(512) void k_final(const float* __restrict__ start_t,
                                               const float* __restrict__ end_t,
                                               float* __restrict__ out) {
    const int tid = threadIdx.x;
    const int b = tid >> 3, j = tid & 7;
    const float L2E = 1.4426950408889634f;
    const float LN2 = 0.6931471805599453f;

    __shared__ float ash[64][8];
    __shared__ float red[64];

    float a = (j < 7) ? (start_t[j] + g_em[(long)b * SS * KK + j]) * L2E : -1e30f;
    ash[b][j] = a;
    __syncthreads();

    for (int c = 0; c < NCHUNK; c++) {
        if (j < 7) {
            float vv[7];
            float mx = -1e30f;
#pragma unroll
            for (int i2 = 0; i2 < 7; i2++) {
                vv[i2] = ash[b][i2] + g_M[(((long)b * NCHUNK + c) * 7 + i2) * 7 + j];
                mx = fmaxf(mx, vv[i2]);
            }
            float sum = 0.f;
#pragma unroll
            for (int i2 = 0; i2 < 7; i2++) sum += exp2f(vv[i2] - mx);
            a = mx + log2f(sum);
        }
        __syncthreads();
        if (j < 7) ash[b][j] = a;
        __syncthreads();
    }

    float z = (j < 7) ? a + end_t[j] * L2E : -1e30f;
    ash[b][j] = z;
    __syncthreads();

    if (j == 0) {
        float mx = -1e30f;
#pragma unroll
        for (int k = 0; k < 7; k++) mx = fmaxf(mx, ash[b][k]);
        float sum = 0.f;
#pragma unroll
        for (int k = 0; k < 7; k++) sum += exp2f(ash[b][k] - mx);
        float denom = (mx + log2f(sum)) * LN2;  // back to natural log
        red[b] = g_num[b] - denom;
    }
    __syncthreads();
    if (tid == 0) {
        float s = 0.f;
#pragma unroll
        for (int b2 = 0; b2 < 64; b2++) s += red[b2];
        out[0] = -s / 64.f;
    }
}

// ---------------------------------------------------------------------------
extern "C" void kernel_launch(void* const* d_in, const int* in_sizes, int n_in,
                              void* d_out, int out_size) {
    const float4* x = (const float4*)d_in[0];
    const void* gt = d_in[1];
    const unsigned char* mask = (const unsigned char*)d_in[2];
    const float* W = (const float*)d_in[3];
    const float* bias = (const float*)d_in[4];
    const float* start_t = (const float*)d_in[5];
    const float* end_t = (const float*)d_in[6];
    const float* trans = (const float*)d_in[7];
    float* out = (float*)d_out;

    const int RPB = 16;
    k_emis<<<(BB * SS) / RPB, 128>>>(x, W, bias, RPB);
    k_num<<<BB, 256>>>(gt, mask, start_t, end_t, trans);
    dim3 g3(NCHUNK, BB);
    k_chunk<<<g3, 64>>>(mask, trans);
    k_final<<<1, 512>>>(start_t, end_t, out);
}

// round 3
// speedup vs baseline: 1.2826x; 1.2826x over previous
#include <cuda_runtime.h>

#define BB 64
#define SS 512
#define HH 1024
#define KK 7
#define NCHUNK 16
#define CHUNK 32
#define RPB 32

typedef unsigned long long ull;

// scratch (allocation-free rule: __device__ globals)
__device__ float g_em[BB * SS * KK];         // emissions
__device__ float g_M[BB * NCHUNK * KK * KK]; // chunk transfer matrices (log2)
__device__ float g_red[BB];                  // per-batch llh
__device__ unsigned int g_cnt = 0;           // self-resetting completion counter

// ---------------------------------------------------------------------------
// fast math helpers
// ---------------------------------------------------------------------------
__device__ __forceinline__ float ex2f(float x) {
    float y; asm("ex2.approx.f32 %0, %1;" : "=f"(y) : "f"(x)); return y;
}
__device__ __forceinline__ float lg2f(float x) {
    float y; asm("lg2.approx.f32 %0, %1;" : "=f"(y) : "f"(x)); return y;
}
__device__ __forceinline__ ull pk2(float lo, float hi) {
    ull r; asm("mov.b64 %0, {%1,%2};" : "=l"(r) : "f"(lo), "f"(hi)); return r;
}
__device__ __forceinline__ void upk2(ull p, float& lo, float& hi) {
    asm("mov.b64 {%0,%1}, %2;" : "=f"(lo), "=f"(hi) : "l"(p));
}
__device__ __forceinline__ ull fma2(ull a, ull b, ull c) {
    ull d; asm("fma.rn.f32x2 %0, %1, %2, %3;" : "=l"(d) : "l"(a), "l"(b), "l"(c));
    return d;
}

// ---------------------------------------------------------------------------
// dtype-width detection (harness may canonicalize bool/int64)
// ---------------------------------------------------------------------------
__device__ __forceinline__ int detect_mask_w(const unsigned char* m) {
    unsigned int or123 = 0, or4 = 0;
#pragma unroll
    for (int off = 0; off < 64; off++) {
        unsigned char v = m[off];
        if (off & 3) or123 |= v;
        else if ((off & 7) == 4) or4 |= v;
    }
    if (or123) return 1;
    return or4 ? 4 : 8;
}
__device__ __forceinline__ int detect_gt_w(const void* gt) {
    const int* v = (const int*)gt;
    int orv = 0;
#pragma unroll
    for (int q = 0; q < 64; q++) orv |= v[2 * q + 1];
    return (orv == 0) ? 2 : 1; // stride in 32-bit words
}

// ---------------------------------------------------------------------------
// K1: emissions = x @ W + b.  grid 1024 x 128 threads, RPB=32 rows/block.
// W slice (56 floats, packed f32x2) in registers; split-k butterfly reduce.
// ---------------------------------------------------------------------------
__global__ __launch_bounds__(128, 4) void k_emis(const float4* __restrict__ x4,
                                                 const float* __restrict__ W,
                                                 const float* __restrict__ bias) {
    const int t = threadIdx.x;
    const int lane = t & 31, warp = t >> 5;
    const long row0 = (long)blockIdx.x * RPB;
    __shared__ float wsum[4][RPB][7];

    ull w01[8], w23[8], w45[8];
    float w6[8];
#pragma unroll
    for (int jj = 0; jj < 2; jj++) {
        const float4* wp4 = (const float4*)(W + (t * 4 + jj * 512) * 7);
        float wb[28];
#pragma unroll
        for (int q4 = 0; q4 < 7; q4++) {
            float4 v = wp4[q4];
            wb[q4 * 4 + 0] = v.x; wb[q4 * 4 + 1] = v.y;
            wb[q4 * 4 + 2] = v.z; wb[q4 * 4 + 3] = v.w;
        }
#pragma unroll
        for (int q = 0; q < 4; q++) {
            int s = jj * 4 + q;
            w01[s] = pk2(wb[q * 7 + 0], wb[q * 7 + 1]);
            w23[s] = pk2(wb[q * 7 + 2], wb[q * 7 + 3]);
            w45[s] = pk2(wb[q * 7 + 4], wb[q * 7 + 5]);
            w6[s] = wb[q * 7 + 6];
        }
    }

    float4 a0 = x4[row0 * 256 + t];
    float4 a1 = x4[row0 * 256 + 128 + t];
    float4 b0 = x4[(row0 + 1) * 256 + t];
    float4 b1 = x4[(row0 + 1) * 256 + 128 + t];

#define DO_ROW(RR, X0, X1)                                                      \
    {                                                                           \
        float xq[8] = {X0.x, X0.y, X0.z, X0.w, X1.x, X1.y, X1.z, X1.w};         \
        ull c01 = 0, c23 = 0, c45 = 0;                                          \
        float c6 = 0.f;                                                         \
        _Pragma("unroll") for (int s = 0; s < 8; s++) {                         \
            ull xx = pk2(xq[s], xq[s]);                                         \
            c01 = fma2(xx, w01[s], c01);                                        \
            c23 = fma2(xx, w23[s], c23);                                        \
            c45 = fma2(xx, w45[s], c45);                                        \
            c6 = fmaf(xq[s], w6[s], c6);                                        \
        }                                                                       \
        float a[7];                                                             \
        upk2(c01, a[0], a[1]); upk2(c23, a[2], a[3]); upk2(c45, a[4], a[5]);    \
        a[6] = c6;                                                              \
        float tt[7];                                                            \
        _Pragma("unroll") for (int k = 0; k < 7; k++)                           \
            tt[k] = __shfl_xor_sync(0xffffffffu, a[k], 16);                     \
        bool hh = (lane & 16);                                                  \
        float v0 = hh ? a[4] + tt[4] : a[0] + tt[0];                            \
        float v1 = hh ? a[5] + tt[5] : a[1] + tt[1];                            \
        float v2 = hh ? a[6] + tt[6] : a[2] + tt[2];                            \
        float v3 = hh ? 0.f : a[3] + tt[3];                                     \
        float s0 = __shfl_xor_sync(0xffffffffu, v0, 8);                         \
        float s1 = __shfl_xor_sync(0xffffffffu, v1, 8);                         \
        float s2 = __shfl_xor_sync(0xffffffffu, v2, 8);                         \
        float s3 = __shfl_xor_sync(0xffffffffu, v3, 8);                         \
        bool b3p = (lane & 8);                                                  \
        float u0 = b3p ? v2 + s2 : v0 + s0;                                     \
        float u1 = b3p ? v3 + s3 : v1 + s1;                                     \
        float p0 = __shfl_xor_sync(0xffffffffu, u0, 4);                         \
        float p1 = __shfl_xor_sync(0xffffffffu, u1, 4);                         \
        float wv = (lane & 4) ? u1 + p1 : u0 + p0;                              \
        wv += __shfl_xor_sync(0xffffffffu, wv, 2);                              \
        wv += __shfl_xor_sync(0xffffffffu, wv, 1);                              \
        int k7 = (lane >> 2) & 7;                                               \
        if (((lane & 3) == 0) && (k7 < 7)) wsum[warp][RR][k7] = wv;             \
    }

    for (int r = 0; r < RPB; r += 2) {
        DO_ROW(r, a0, a1);
        if (r + 2 < RPB) {
            a0 = x4[(row0 + r + 2) * 256 + t];
            a1 = x4[(row0 + r + 2) * 256 + 128 + t];
        }
        DO_ROW(r + 1, b0, b1);
        if (r + 3 < RPB) {
            b0 = x4[(row0 + r + 3) * 256 + t];
            b1 = x4[(row0 + r + 3) * 256 + 128 + t];
        }
    }
#undef DO_ROW
    __syncthreads();
    for (int idx = t; idx < RPB * 7; idx += 128) {
        int r = idx / 7, k = idx - r * 7;
        g_em[(row0 + r) * 7 + k] =
            wsum[0][r][k] + wsum[1][r][k] + wsum[2][r][k] + wsum[3][r][k] + bias[k];
    }
}

// ---------------------------------------------------------------------------
// K2: per-chunk 7x7 transfer matrix, scaled forward, pure warp-level.
// thread (i,j): row i lives in one 8-lane shuffle group. No syncthreads in loop.
// Renorm every 4 steps. grid = (NCHUNK, BB) x 64 threads.
// ---------------------------------------------------------------------------
__global__ __launch_bounds__(64) void k_chunk(const unsigned char* __restrict__ mask,
                                              const float* __restrict__ trans) {
    const int c = blockIdx.x, b = blockIdx.y;
    const int tid = threadIdx.x;
    const int j = tid & 7, i = (tid >> 3) & 7;
    const bool act = (i < 7) && (j < 7);
    const float L2E = 1.4426950408889634f;

    __shared__ int s_mw;
    if (tid == 0) s_mw = detect_mask_w(mask);
    __syncthreads();
    const int mw = s_mw;

    const int jj = (j < 7) ? j : 0;
    float Tr[7];
#pragma unroll
    for (int k = 0; k < 7; k++)
        Tr[k] = act ? ex2f(trans[k * 7 + jj] * L2E) : 0.f;

    float v = (act && i == j) ? 1.f : 0.f;
    int mexp = 0;

    const int t0 = 1 + c * CHUNK;
    const int t1 = (t0 + CHUNK < SS) ? (t0 + CHUNK) : SS;
    const long base = (long)b * SS;

    float em_n = g_em[(base + t0) * KK + jj];
    int mk_n = mask[(base + t0) * mw];

    for (int tt = t0; tt < t1; tt++) {
        const float em_c = em_n;
        const int mk = mk_n;
        if (tt + 1 < t1) {
            em_n = g_em[(base + tt + 1) * KK + jj];
            mk_n = mask[(base + tt + 1) * mw];
        }
        float e = ex2f(em_c * L2E);
        float nv = 0.f;
#pragma unroll
        for (int k = 0; k < 7; k++)
            nv = fmaf(__shfl_sync(0xffffffffu, v, k, 8), Tr[k], nv);
        if (mk) v = nv * e;

        int st = tt - t0;
        if (((st & 3) == 3) || (tt == t1 - 1)) {
            float rs = v;
            rs += __shfl_xor_sync(0xffffffffu, rs, 4, 8);
            rs += __shfl_xor_sync(0xffffffffu, rs, 2, 8);
            rs += __shfl_xor_sync(0xffffffffu, rs, 1, 8);
            int eb = ((__float_as_int(rs) >> 23) & 255) - 127;
            eb = (rs > 0.f) ? eb : 0;
            v *= __int_as_float((127 - eb) << 23); // * 2^-eb
            mexp += eb;
        }
    }
    if (act)
        g_M[(((long)b * NCHUNK + c) * 7 + i) * 7 + j] = (float)mexp + lg2f(v);
}

// ---------------------------------------------------------------------------
// K3: per-batch numerator + chunk-matrix combination + llh; last block reduces.
// grid = BB x 64 threads.
// ---------------------------------------------------------------------------
__global__ __launch_bounds__(64) void k_post(const void* __restrict__ gt,
                                             const unsigned char* __restrict__ mask,
                                             const float* __restrict__ start_t,
                                             const float* __restrict__ end_t,
                                             const float* __restrict__ trans,
                                             float* __restrict__ out) {
    const int b = blockIdx.x, tid = threadIdx.x;
    const float L2E = 1.4426950408889634f, LN2 = 0.6931471805599453f;

    __shared__ float Msh[NCHUNK][56];
    __shared__ float s_part[2];
    __shared__ int c_part[2];
    __shared__ float s_num;
    __shared__ int s_gw, s_mw, s_isLast;

    if (tid == 0) { s_gw = detect_gt_w(gt); s_mw = detect_mask_w(mask); }

    // prefetch chunk matrices into smem (padded rows)
    const float* Mb = g_M + (long)b * NCHUNK * 49;
    for (int idx = tid; idx < NCHUNK * 49; idx += 64) {
        int c = idx / 49, rem = idx - c * 49;
        Msh[c][rem] = Mb[idx];
    }
    __syncthreads();
    const int gw = s_gw, mw = s_mw;

    // numerator: 8 timesteps per thread
    const long gbase = (long)b * SS;
    const float* emb = g_em + gbase * KK;
    float s = 0.f;
    int cnt = 0;
#pragma unroll
    for (int q = 0; q < 8; q++) {
        int t_ = tid * 8 + q;
        int gc = ((const int*)gt)[(gbase + t_) * gw];
        int m = mask[(gbase + t_) * mw] ? 1 : 0;
        cnt += m;
        if (t_ == 0) {
            s += start_t[gc] + emb[gc];
        } else {
            int gp = ((const int*)gt)[(gbase + t_ - 1) * gw];
            s += m ? (trans[gp * 7 + gc] + emb[t_ * 7 + gc]) : 0.f;
        }
    }
#pragma unroll
    for (int off = 16; off; off >>= 1) {
        s += __shfl_xor_sync(0xffffffffu, s, off);
        cnt += __shfl_xor_sync(0xffffffffu, cnt, off);
    }
    if ((tid & 31) == 0) { s_part[tid >> 5] = s; c_part[tid >> 5] = cnt; }
    __syncthreads();
    if (tid == 0) {
        float st = s_part[0] + s_part[1];
        int ct = c_part[0] + c_part[1];
        s_num = st + end_t[((const int*)gt)[(gbase + ct - 1) * gw]];
    }
    __syncthreads();

    // recursion on warp 0 (8-lane groups; lanes 8..31 compute harmless copies)
    if (tid < 32) {
        const int j = tid & 7;
        float a = (j < 7) ? (start_t[j] + emb[j]) * L2E : -1e30f;
        for (int c = 0; c < NCHUNK; c++) {
            float mx = -1e30f;
            float vv[7];
#pragma unroll
            for (int i2 = 0; i2 < 7; i2++) {
                float ai = __shfl_sync(0xffffffffu, a, i2, 8);
                vv[i2] = ai + Msh[c][i2 * 7 + j];
                mx = fmaxf(mx, vv[i2]);
            }
            float sum = 0.f;
#pragma unroll
            for (int i2 = 0; i2 < 7; i2++) sum += ex2f(vv[i2] - mx);
            float anew = mx + lg2f(sum);
            a = (j < 7) ? anew : -1e30f;
        }
        float z = (j < 7) ? a + end_t[j] * L2E : -1e30f;
        float mz = z;
        mz = fmaxf(mz, __shfl_xor_sync(0xffffffffu, mz, 4, 8));
        mz = fmaxf(mz, __shfl_xor_sync(0xffffffffu, mz, 2, 8));
        mz = fmaxf(mz, __shfl_xor_sync(0xffffffffu, mz, 1, 8));
        float se = ex2f(z - mz);
        se += __shfl_xor_sync(0xffffffffu, se, 4, 8);
        se += __shfl_xor_sync(0xffffffffu, se, 2, 8);
        se += __shfl_xor_sync(0xffffffffu, se, 1, 8);
        float denom = (mz + lg2f(se)) * LN2;

        if (tid == 0) {
            g_red[b] = s_num - denom;
            __threadfence();
            unsigned int old = atomicInc(&g_cnt, BB - 1);
            s_isLast = (old == BB - 1) ? 1 : 0;
        }
    }
    __syncthreads();

    if (s_isLast) {
        __threadfence();
        float r = __ldcg(&g_red[tid]);
#pragma unroll
        for (int off = 16; off; off >>= 1)
            r += __shfl_xor_sync(0xffffffffu, r, off);
        if ((tid & 31) == 0) s_part[tid >> 5] = r;
        __syncthreads();
        if (tid == 0) out[0] = -(s_part[0] + s_part[1]) / (float)BB;
    }
}

// ---------------------------------------------------------------------------
extern "C" void kernel_launch(void* const* d_in, const int* in_sizes, int n_in,
                              void* d_out, int out_size) {
    const float4* x = (const float4*)d_in[0];
    const void* gt = d_in[1];
    const unsigned char* mask = (const unsigned char*)d_in[2];
    const float* W = (const float*)d_in[3];
    const float* bias = (const float*)d_in[4];
    const float* start_t = (const float*)d_in[5];
    const float* end_t = (const float*)d_in[6];
    const float* trans = (const float*)d_in[7];
    float* out = (float*)d_out;

    k_emis<<<(BB * SS) / RPB, 128>>>(x, W, bias);
    dim3 g3(NCHUNK, BB);
    k_chunk<<<g3, 64>>>(mask, trans);
    k_post<<<BB, 64>>>(gt, mask, start_t, end_t, trans, out);
}

// round 4
// speedup vs baseline: 1.3463x; 1.0497x over previous
#include <cuda_runtime.h>

#define BB 64
#define SS 512
#define HH 1024
#define KK 7
#define NCHUNK 16
#define RPB 32

typedef unsigned long long ull;

// scratch (allocation-free rule: __device__ globals)
__device__ float g_M[BB * NCHUNK * KK * KK]; // chunk transfer matrices (log2)
__device__ float g_nump[BB * NCHUNK];        // numerator partials
__device__ int   g_cntp[BB * NCHUNK];        // mask-count partials
__device__ float g_em0[BB * KK];             // emissions row 0 per batch
__device__ float g_red[BB];                  // per-batch llh
__device__ unsigned int g_cnt = 0;           // self-resetting completion counter

// ---------------------------------------------------------------------------
// fast math helpers
// ---------------------------------------------------------------------------
__device__ __forceinline__ float ex2f(float x) {
    float y; asm("ex2.approx.f32 %0, %1;" : "=f"(y) : "f"(x)); return y;
}
__device__ __forceinline__ float lg2f(float x) {
    float y; asm("lg2.approx.f32 %0, %1;" : "=f"(y) : "f"(x)); return y;
}
__device__ __forceinline__ ull pk2(float lo, float hi) {
    ull r; asm("mov.b64 %0, {%1,%2};" : "=l"(r) : "f"(lo), "f"(hi)); return r;
}
__device__ __forceinline__ void upk2(ull p, float& lo, float& hi) {
    asm("mov.b64 {%0,%1}, %2;" : "=f"(lo), "=f"(hi) : "l"(p));
}
__device__ __forceinline__ ull fma2(ull a, ull b, ull c) {
    ull d; asm("fma.rn.f32x2 %0, %1, %2, %3;" : "=l"(d) : "l"(a), "l"(b), "l"(c));
    return d;
}

// ---------------------------------------------------------------------------
// dtype-width detection (harness may canonicalize bool/int64)
// ---------------------------------------------------------------------------
__device__ __forceinline__ int detect_mask_w(const unsigned char* m) {
    unsigned int or123 = 0, or4 = 0;
#pragma unroll
    for (int off = 0; off < 64; off++) {
        unsigned char v = m[off];
        if (off & 3) or123 |= v;
        else if ((off & 7) == 4) or4 |= v;
    }
    if (or123) return 1;
    return or4 ? 4 : 8;
}
__device__ __forceinline__ int detect_gt_w(const void* gt) {
    const int* v = (const int*)gt;
    int orv = 0;
#pragma unroll
    for (int q = 0; q < 64; q++) orv |= v[2 * q + 1];
    return (orv == 0) ? 2 : 1; // stride in 32-bit words
}

// ---------------------------------------------------------------------------
// K1 fused: emissions (DRAM-bound GEMV) + chunk transfer matrices + numerator
// partials. grid = BB*NCHUNK blocks x 128 threads; block g handles batch
// b=g>>4, chunk c=g&15, i.e. rows s in [32c, 32c+32).
// ---------------------------------------------------------------------------
__global__ __launch_bounds__(128, 3) void k_fused(const float4* __restrict__ x4,
                                                  const float* __restrict__ W,
                                                  const float* __restrict__ bias,
                                                  const void* __restrict__ gt,
                                                  const unsigned char* __restrict__ mask,
                                                  const float* __restrict__ start_t,
                                                  const float* __restrict__ trans) {
    const int t = threadIdx.x;
    const int lane = t & 31, warp = t >> 5;
    const int g = blockIdx.x;
    const int b = g >> 4, c = g & 15;
    const long row0 = (long)g * RPB;
    const float L2E = 1.4426950408889634f;

    __shared__ float wsum[4][RPB][7];
    __shared__ float em_s[RPB][8];
    __shared__ int msk_s[RPB];
    __shared__ int s_mw, s_gw;

    if (t == 0) { s_mw = detect_mask_w(mask); s_gw = detect_gt_w(gt); }

    // ---- W slice (56 floats) into registers, packed f32x2 ----
    ull w01[8], w23[8], w45[8];
    float w6[8];
#pragma unroll
    for (int jj = 0; jj < 2; jj++) {
        const float4* wp4 = (const float4*)(W + (t * 4 + jj * 512) * 7);
        float wb[28];
#pragma unroll
        for (int q4 = 0; q4 < 7; q4++) {
            float4 v = wp4[q4];
            wb[q4 * 4 + 0] = v.x; wb[q4 * 4 + 1] = v.y;
            wb[q4 * 4 + 2] = v.z; wb[q4 * 4 + 3] = v.w;
        }
#pragma unroll
        for (int q = 0; q < 4; q++) {
            int s = jj * 4 + q;
            w01[s] = pk2(wb[q * 7 + 0], wb[q * 7 + 1]);
            w23[s] = pk2(wb[q * 7 + 2], wb[q * 7 + 3]);
            w45[s] = pk2(wb[q * 7 + 4], wb[q * 7 + 5]);
            w6[s] = wb[q * 7 + 6];
        }
    }

#define DO_ROW(RR, X0, X1)                                                      \
    {                                                                           \
        float xq[8] = {X0.x, X0.y, X0.z, X0.w, X1.x, X1.y, X1.z, X1.w};         \
        ull c01 = 0, c23 = 0, c45 = 0;                                          \
        float c6 = 0.f;                                                         \
        _Pragma("unroll") for (int s = 0; s < 8; s++) {                         \
            ull xx = pk2(xq[s], xq[s]);                                         \
            c01 = fma2(xx, w01[s], c01);                                        \
            c23 = fma2(xx, w23[s], c23);                                        \
            c45 = fma2(xx, w45[s], c45);                                        \
            c6 = fmaf(xq[s], w6[s], c6);                                        \
        }                                                                       \
        float a[7];                                                             \
        upk2(c01, a[0], a[1]); upk2(c23, a[2], a[3]); upk2(c45, a[4], a[5]);    \
        a[6] = c6;                                                              \
        float tt[7];                                                            \
        _Pragma("unroll") for (int k = 0; k < 7; k++)                           \
            tt[k] = __shfl_xor_sync(0xffffffffu, a[k], 16);                     \
        bool hh = (lane & 16);                                                  \
        float v0 = hh ? a[4] + tt[4] : a[0] + tt[0];                            \
        float v1 = hh ? a[5] + tt[5] : a[1] + tt[1];                            \
        float v2 = hh ? a[6] + tt[6] : a[2] + tt[2];                            \
        float v3 = hh ? 0.f : a[3] + tt[3];                                     \
        float s0 = __shfl_xor_sync(0xffffffffu, v0, 8);                         \
        float s1 = __shfl_xor_sync(0xffffffffu, v1, 8);                         \
        float s2 = __shfl_xor_sync(0xffffffffu, v2, 8);                         \
        float s3 = __shfl_xor_sync(0xffffffffu, v3, 8);                         \
        bool b3p = (lane & 8);                                                  \
        float u0 = b3p ? v2 + s2 : v0 + s0;                                     \
        float u1 = b3p ? v3 + s3 : v1 + s1;                                     \
        float p0 = __shfl_xor_sync(0xffffffffu, u0, 4);                         \
        float p1 = __shfl_xor_sync(0xffffffffu, u1, 4);                         \
        float wv = (lane & 4) ? u1 + p1 : u0 + p0;                              \
        wv += __shfl_xor_sync(0xffffffffu, wv, 2);                              \
        wv += __shfl_xor_sync(0xffffffffu, wv, 1);                              \
        int k7 = (lane >> 2) & 7;                                               \
        if (((lane & 3) == 0) && (k7 < 7)) wsum[warp][RR][k7] = wv;             \
    }

    // ---- main loop: 4-row-deep prefetch pipeline ----
    float4 buf[4][2];
#pragma unroll
    for (int u = 0; u < 4; u++) {
        buf[u][0] = x4[(row0 + u) * 256 + t];
        buf[u][1] = x4[(row0 + u) * 256 + 128 + t];
    }
#pragma unroll 1
    for (int rb = 0; rb < RPB; rb += 4) {
#pragma unroll
        for (int u = 0; u < 4; u++) {
            const int r = rb + u;
            float4 X0 = buf[u][0], X1 = buf[u][1];
            if (r + 4 < RPB) {
                buf[u][0] = x4[(row0 + r + 4) * 256 + t];
                buf[u][1] = x4[(row0 + r + 4) * 256 + 128 + t];
            }
            DO_ROW(r, X0, X1);
        }
    }
#undef DO_ROW
    __syncthreads();

    // ---- combine warp partials -> em_s; fill msk_s; write em0 ----
    const int mw = s_mw, gw = s_gw;
    for (int idx = t; idx < RPB * 7; idx += 128) {
        int r = idx / 7, k = idx - r * 7;
        float e = wsum[0][r][k] + wsum[1][r][k] + wsum[2][r][k] + wsum[3][r][k] + bias[k];
        em_s[r][k] = e;
        if (c == 0 && idx < 7) g_em0[b * 7 + idx] = e;
    }
    if (t < RPB) msk_s[t] = mask[((long)b * SS + c * RPB + t) * mw] ? 1 : 0;
    __syncthreads();

    // ---- warps 0-1: chunk transfer matrix (scaled forward) ----
    if (warp < 2) {
        const int j = lane & 7;
        const int i = (lane >> 3) + warp * 4;
        const bool act = (j < 7) && (i < 7);
        const int jj = (j < 7) ? j : 0;
        float Tr[7];
#pragma unroll
        for (int k = 0; k < 7; k++)
            Tr[k] = act ? ex2f(trans[k * 7 + jj] * L2E) : 0.f;

        float v = (act && i == j) ? 1.f : 0.f;
        int mexp = 0;
        const int lt0 = (c == 0) ? 1 : 0;
        for (int lt = lt0; lt < RPB; lt++) {
            float e = ex2f(em_s[lt][jj] * L2E);
            int mk = msk_s[lt];
            float nv = 0.f;
#pragma unroll
            for (int k = 0; k < 7; k++)
                nv = fmaf(__shfl_sync(0xffffffffu, v, k, 8), Tr[k], nv);
            if (mk) v = nv * e;
            if (((lt & 3) == 3) || (lt == RPB - 1)) {
                float rs = v;
                rs += __shfl_xor_sync(0xffffffffu, rs, 4, 8);
                rs += __shfl_xor_sync(0xffffffffu, rs, 2, 8);
                rs += __shfl_xor_sync(0xffffffffu, rs, 1, 8);
                int eb = ((__float_as_int(rs) >> 23) & 255) - 127;
                eb = (rs > 0.f) ? eb : 0;
                v *= __int_as_float((127 - eb) << 23); // * 2^-eb
                mexp += eb;
            }
        }
        if (act)
            g_M[((long)g * 7 + i) * 7 + j] = (float)mexp + lg2f(v);
    }

    // ---- warp 2: numerator + count partial for this chunk's rows ----
    if (warp == 2) {
        const int s = c * RPB + lane; // absolute timestep
        const int m = msk_s[lane];
        const int gc = ((const int*)gt)[((long)b * SS + s) * gw];
        float contrib;
        if (s == 0) {
            contrib = start_t[gc] + em_s[0][gc];
        } else {
            const int gp = ((const int*)gt)[((long)b * SS + s - 1) * gw];
            contrib = m ? (trans[gp * 7 + gc] + em_s[lane][gc]) : 0.f;
        }
        float sum = contrib;
        int cnt = m;
#pragma unroll
        for (int off = 16; off; off >>= 1) {
            sum += __shfl_xor_sync(0xffffffffu, sum, off);
            cnt += __shfl_xor_sync(0xffffffffu, cnt, off);
        }
        if (lane == 0) { g_nump[g] = sum; g_cntp[g] = cnt; }
    }
}

// ---------------------------------------------------------------------------
// K2: per-batch combine: numerator total, 16-step log2 LSE composition, llh;
// last block reduces to the scalar. grid = BB x 64 threads.
// ---------------------------------------------------------------------------
__global__ __launch_bounds__(64) void k_post(const void* __restrict__ gt,
                                             const float* __restrict__ start_t,
                                             const float* __restrict__ end_t,
                                             float* __restrict__ out) {
    const int b = blockIdx.x, tid = threadIdx.x;
    const float L2E = 1.4426950408889634f, LN2 = 0.6931471805599453f;

    __shared__ float Msh[NCHUNK][49];
    __shared__ float s_num, s_part[2];
    __shared__ int s_gw, s_isLast;

    if (tid == 0) s_gw = detect_gt_w(gt);

    const float* Mb = g_M + (long)b * NCHUNK * 49;
    for (int idx = tid; idx < NCHUNK * 49; idx += 64) {
        int cc = idx / 49, rem = idx - cc * 49;
        Msh[cc][rem] = Mb[idx];
    }

    float p = 0.f;
    int cn = 0;
    if (tid < NCHUNK) { p = g_nump[b * NCHUNK + tid]; cn = g_cntp[b * NCHUNK + tid]; }
    __syncthreads();

    if (tid < 32) {
#pragma unroll
        for (int off = 8; off; off >>= 1) {
            p += __shfl_xor_sync(0xffffffffu, p, off);
            cn += __shfl_xor_sync(0xffffffffu, cn, off);
        }
        if (tid == 0)
            s_num = p + end_t[((const int*)gt)[((long)b * SS + cn - 1) * s_gw]];
    }
    __syncthreads();

    if (tid < 32) {
        const int j = tid & 7;
        float a = (j < 7) ? (start_t[j] + g_em0[b * 7 + j]) * L2E : -1e30f;
        for (int cc = 0; cc < NCHUNK; cc++) {
            float mx = -1e30f;
            float vv[7];
#pragma unroll
            for (int i2 = 0; i2 < 7; i2++) {
                float ai = __shfl_sync(0xffffffffu, a, i2, 8);
                vv[i2] = ai + Msh[cc][i2 * 7 + j];
                mx = fmaxf(mx, vv[i2]);
            }
            float sum = 0.f;
#pragma unroll
            for (int i2 = 0; i2 < 7; i2++) sum += ex2f(vv[i2] - mx);
            float anew = mx + lg2f(sum);
            a = (j < 7) ? anew : -1e30f;
        }
        float z = (j < 7) ? a + end_t[j] * L2E : -1e30f;
        float mz = z;
        mz = fmaxf(mz, __shfl_xor_sync(0xffffffffu, mz, 4, 8));
        mz = fmaxf(mz, __shfl_xor_sync(0xffffffffu, mz, 2, 8));
        mz = fmaxf(mz, __shfl_xor_sync(0xffffffffu, mz, 1, 8));
        float se = ex2f(z - mz);
        se += __shfl_xor_sync(0xffffffffu, se, 4, 8);
        se += __shfl_xor_sync(0xffffffffu, se, 2, 8);
        se += __shfl_xor_sync(0xffffffffu, se, 1, 8);
        float denom = (mz + lg2f(se)) * LN2;

        if (tid == 0) {
            g_red[b] = s_num - denom;
            __threadfence();
            unsigned int old = atomicInc(&g_cnt, BB - 1);
            s_isLast = (old == BB - 1) ? 1 : 0;
        }
    }
    __syncthreads();

    if (s_isLast) {
        __threadfence();
        float r = __ldcg(&g_red[tid]);
#pragma unroll
        for (int off = 16; off; off >>= 1)
            r += __shfl_xor_sync(0xffffffffu, r, off);
        if ((tid & 31) == 0) s_part[tid >> 5] = r;
        __syncthreads();
        if (tid == 0) out[0] = -(s_part[0] + s_part[1]) / (float)BB;
    }
}

// ---------------------------------------------------------------------------
extern "C" void kernel_launch(void* const* d_in, const int* in_sizes, int n_in,
                              void* d_out, int out_size) {
    const float4* x = (const float4*)d_in[0];
    const void* gt = d_in[1];
    const unsigned char* mask = (const unsigned char*)d_in[2];
    const float* W = (const float*)d_in[3];
    const float* bias = (const float*)d_in[4];
    const float* start_t = (const float*)d_in[5];
    const float* end_t = (const float*)d_in[6];
    const float* trans = (const float*)d_in[7];
    float* out = (float*)d_out;

    k_fused<<<BB * NCHUNK, 128>>>(x, W, bias, gt, mask, start_t, trans);
    k_post<<<BB, 64>>>(gt, start_t, end_t, out);
}